// round 13
// baseline (speedup 1.0000x reference)
#include <cuda_runtime.h>
#include <cuda_bf16.h>
#include <math.h>
#include <stdint.h>

#define BB 2
#define LL 1024
#define DD 768
#define HH 12
#define LATD 512
#define MM (BB*LL)   // 2048
#define BHL (BB*HH*LL)
#define NBIG 3200    // merged: 2304 qkv | 768 og | 48 reso | 80 pad
#define PI_F 3.14159265358979323846f

// ================= scratch (static device arrays; no allocation) =================
__device__ __align__(256) float g_latent[MM*LATD];
__device__ __align__(256) float g_qkv[MM*3*DD];
__device__ __align__(256) float g_reso[MM*128];        // padded stride 128
__device__ __align__(256) float g_og[MM*DD];
__device__ __align__(256) float g_cA[BHL];
__device__ __align__(256) float g_cB[BHL];
__device__ __align__(256) float g_df[BHL];
__device__ __align__(256) float g_o[MM*DD];
// bf16 hi/lo attention operands
__device__ __align__(256) __nv_bfloat16 g_qh[BHL*64], g_ql[BHL*64];
__device__ __align__(256) __nv_bfloat16 g_kh[BHL*64], g_kl[BHL*64];
__device__ __align__(256) __nv_bfloat16 g_vh[BHL*72], g_vl[BHL*72];  // V' (cA*v | cB | pad)
// bf16 hi/lo GEMM operands
__device__ __align__(256) __nv_bfloat16 g_xn_h[MM*DD],   g_xn_l[MM*DD];
__device__ __align__(256) __nv_bfloat16 g_lat_h[MM*LATD], g_lat_l[MM*LATD];
__device__ __align__(256) __nv_bfloat16 g_on_h[MM*DD],   g_on_l[MM*DD];
__device__ __align__(256) __nv_bfloat16 g_wc_h[LATD*DD],  g_wc_l[LATD*DD];     // [512][768]
__device__ __align__(256) __nv_bfloat16 g_wb_h[NBIG*LATD],g_wb_l[NBIG*LATD];   // [3200][512]
__device__ __align__(256) __nv_bfloat16 g_wp_h[DD*DD],    g_wp_l[DD*DD];       // [768][768]

// ================= PTX helpers (baseline sm_80+ features only) =================
__device__ __forceinline__ uint32_t smem_u32(const void* p) {
    uint32_t a;
    asm("{ .reg .u64 t; cvta.to.shared.u64 t, %1; cvt.u32.u64 %0, t; }" : "=r"(a) : "l"(p));
    return a;
}
__device__ __forceinline__ void cp16(uint32_t dst, const void* src) {
    asm volatile("cp.async.cg.shared.global [%0], [%1], 16;" :: "r"(dst), "l"(src));
}
__device__ __forceinline__ void cp_commit() { asm volatile("cp.async.commit_group;" ::: "memory"); }
template<int N> __device__ __forceinline__ void cp_wait() {
    asm volatile("cp.async.wait_group %0;" :: "n"(N) : "memory");
}
__device__ __forceinline__ void ldsm4(uint32_t* r, uint32_t addr) {
    asm volatile("ldmatrix.sync.aligned.m8n8.x4.shared.b16 {%0,%1,%2,%3}, [%4];"
        : "=r"(r[0]), "=r"(r[1]), "=r"(r[2]), "=r"(r[3]) : "r"(addr));
}
__device__ __forceinline__ void ldsm2(uint32_t* r, uint32_t addr) {
    asm volatile("ldmatrix.sync.aligned.m8n8.x2.shared.b16 {%0,%1}, [%2];"
        : "=r"(r[0]), "=r"(r[1]) : "r"(addr));
}
__device__ __forceinline__ void ldsm2t(uint32_t* r, uint32_t addr) {
    asm volatile("ldmatrix.sync.aligned.m8n8.x2.trans.shared.b16 {%0,%1}, [%2];"
        : "=r"(r[0]), "=r"(r[1]) : "r"(addr));
}
__device__ __forceinline__ void mma16816(float* d, const uint32_t* a, const uint32_t* b) {
    asm volatile(
        "mma.sync.aligned.m16n8k16.row.col.f32.bf16.bf16.f32 "
        "{%0,%1,%2,%3}, {%4,%5,%6,%7}, {%8,%9}, {%0,%1,%2,%3};"
        : "+f"(d[0]), "+f"(d[1]), "+f"(d[2]), "+f"(d[3])
        : "r"(a[0]), "r"(a[1]), "r"(a[2]), "r"(a[3]), "r"(b[0]), "r"(b[1]));
}
__device__ __forceinline__ void hilo2(float a, float b, uint32_t& hi, uint32_t& lo) {
    __nv_bfloat16 ha = __float2bfloat16(a), hb = __float2bfloat16(b);
    __nv_bfloat16 la = __float2bfloat16(a - __bfloat162float(ha));
    __nv_bfloat16 lb = __float2bfloat16(b - __bfloat162float(hb));
    hi = (uint32_t)__bfloat16_as_ushort(ha) | ((uint32_t)__bfloat16_as_ushort(hb) << 16);
    lo = (uint32_t)__bfloat16_as_ushort(la) | ((uint32_t)__bfloat16_as_ushort(lb) << 16);
}
__device__ __forceinline__ void st_hilo(__nv_bfloat16* hi, __nv_bfloat16* lo, size_t idx, float v) {
    __nv_bfloat16 h = __float2bfloat16(v);
    hi[idx] = h;
    lo[idx] = __float2bfloat16(v - __bfloat162float(h));
}

// ================= HMMA GEMM: C[M,N] = A[M,K] @ B[N,K]^T =================
// act: 0=none, 1=silu, 2=mul aux, 3=silu+emit hi/lo, 4=merged-segment epilogue
// 4 warps (2m x 2n), warp tile (BM/2)x64 -> 85 B of smem per MMA (vs 128 at x32 tiles).
#define MATB_B 10240               // 128 rows * 40 bf16 * 2B

template<int BM>
__global__ __launch_bounds__(128, 2)
void mma_gemm(const __nv_bfloat16* __restrict__ Ahi, const __nv_bfloat16* __restrict__ Alo,
              const __nv_bfloat16* __restrict__ Bhi, const __nv_bfloat16* __restrict__ Blo,
              float* __restrict__ C, int N, int K, int act,
              const float* __restrict__ aux,
              __nv_bfloat16* __restrict__ Chi, __nv_bfloat16* __restrict__ Clo)
{
    constexpr int MATB_A = BM * 80;
    constexpr int BUFB = 2*MATB_A + 2*MATB_B;
    constexpr int MT = BM / 32;          // 16-row tiles per warp
    extern __shared__ __align__(128) char smem[];
    uint32_t sb = smem_u32(smem);
    int tid = threadIdx.x;
    int wid = tid >> 5, lane = tid & 31;
    int row0 = blockIdx.y * BM;
    int n0   = blockIdx.x * 128;
    int wm0 = (wid & 1) * (BM/2);
    int wn0 = (wid >> 1) * 64;

    const __nv_bfloat16* amats[2] = { Ahi + (size_t)row0 * K, Alo + (size_t)row0 * K };
    const __nv_bfloat16* bmats[2] = { Bhi + (size_t)n0   * K, Blo + (size_t)n0   * K };

    float acc[MT][8][4];
    #pragma unroll
    for (int mt = 0; mt < MT; mt++)
        #pragma unroll
        for (int nt = 0; nt < 8; nt++)
            #pragma unroll
            for (int i = 0; i < 4; i++) acc[mt][nt][i] = 0.f;

    auto fill = [&](int c, int buf) {
        int k0 = c * 32;
        uint32_t dbase = sb + buf * BUFB;
        #pragma unroll
        for (int m = 0; m < 2; m++) {
            const __nv_bfloat16* srcm = amats[m] + k0;
            #pragma unroll
            for (int g = 0; g < BM/32; g++) {      // BM*4 cp16 per matrix, 128 threads
                int idx = g * 128 + tid;
                int row = idx >> 2, q = idx & 3;
                cp16(dbase + m * MATB_A + row * 80 + q * 16,
                     srcm + (size_t)row * K + q * 8);
            }
        }
        #pragma unroll
        for (int m = 0; m < 2; m++) {
            const __nv_bfloat16* srcm = bmats[m] + k0;
            #pragma unroll
            for (int g = 0; g < 4; g++) {          // 512 cp16 per matrix
                int idx = g * 128 + tid;
                int row = idx >> 2, q = idx & 3;
                cp16(dbase + 2*MATB_A + m * MATB_B + row * 80 + q * 16,
                     srcm + (size_t)row * K + q * 8);
            }
        }
    };

    int NC = K >> 5;
    fill(0, 0); cp_commit();

    for (int c = 0; c < NC; c++) {
        if (c + 1 < NC) { fill(c + 1, (c + 1) & 1); cp_commit(); cp_wait<1>(); }
        else cp_wait<0>();
        __syncthreads();

        uint32_t base = sb + (c & 1) * BUFB;
        #pragma unroll
        for (int ks = 0; ks < 2; ks++) {
            uint32_t ah[MT][4], al[MT][4], bh[8][2], bl[8][2];
            int arow = wm0 + (lane & 15);
            int acol = ks * 16 + (lane >> 4) * 8;
            #pragma unroll
            for (int mt = 0; mt < MT; mt++) {
                uint32_t ad = base + (arow + mt * 16) * 80 + acol * 2;
                ldsm4(ah[mt], ad);
                ldsm4(al[mt], ad + MATB_A);
            }
            int brow = wn0 + (lane & 7);
            int bcol = ks * 16 + ((lane >> 3) & 1) * 8;
            #pragma unroll
            for (int nt = 0; nt < 8; nt++) {
                uint32_t bd = base + 2*MATB_A + (brow + nt * 8) * 80 + bcol * 2;
                ldsm2(bh[nt], bd);
                ldsm2(bl[nt], bd + MATB_B);
            }
            #pragma unroll
            for (int mt = 0; mt < MT; mt++)
                #pragma unroll
                for (int nt = 0; nt < 8; nt++) {
                    mma16816(acc[mt][nt], ah[mt], bh[nt]);
                    mma16816(acc[mt][nt], ah[mt], bl[nt]);
                    mma16816(acc[mt][nt], al[mt], bh[nt]);
                }
        }
        __syncthreads();
    }

    // ---- epilogue (merged-segment dispatch for act==4)
    float* Cp = C; int Nout = N; int coff = n0; int a = act;
    if (act == 4) {
        if (n0 < 2304)       { Cp = g_qkv;  Nout = 2304; coff = n0;        a = 0; }
        else if (n0 < 3072)  { Cp = g_og;   Nout = 768;  coff = n0 - 2304; a = 1; }
        else                 { Cp = g_reso; Nout = 128;  coff = 0;         a = 0; }
    }
    #pragma unroll
    for (int mt = 0; mt < MT; mt++) {
        #pragma unroll
        for (int nt = 0; nt < 8; nt++) {
            int r1 = row0 + wm0 + mt * 16 + (lane >> 2);
            int ct = wn0 + nt * 8 + (lane & 3) * 2;
            #pragma unroll
            for (int hf = 0; hf < 2; hf++) {
                int rr = r1 + hf * 8;
                float v0 = acc[mt][nt][hf * 2], v1 = acc[mt][nt][hf * 2 + 1];
                size_t gidx = (size_t)rr * Nout + coff + ct;
                if (a == 1 || a == 3) {
                    v0 = v0 / (1.f + expf(-v0));
                    v1 = v1 / (1.f + expf(-v1));
                } else if (a == 2) {
                    float2 ax = *(const float2*)(aux + gidx);
                    v0 *= ax.x; v1 *= ax.y;
                }
                *(float2*)(Cp + gidx) = make_float2(v0, v1);
                if (a == 3) {
                    __nv_bfloat16 h0 = __float2bfloat16(v0);
                    __nv_bfloat16 h1 = __float2bfloat16(v1);
                    __nv_bfloat162 hh; hh.x = h0; hh.y = h1;
                    *(__nv_bfloat162*)(Chi + gidx) = hh;
                    __nv_bfloat162 ll;
                    ll.x = __float2bfloat16(v0 - __bfloat162float(h0));
                    ll.y = __float2bfloat16(v1 - __bfloat162float(h1));
                    *(__nv_bfloat162*)(Clo + gidx) = ll;
                }
            }
        }
    }
}

// ================= RMSNorm over 768 -> bf16 hi/lo =================
__global__ __launch_bounds__(256) void rms_hilo(const float* __restrict__ x,
                                                const float* __restrict__ w,
                                                __nv_bfloat16* __restrict__ hi,
                                                __nv_bfloat16* __restrict__ lo) {
    __shared__ float red[256];
    int row = blockIdx.x;
    const float* xr = x + (size_t)row * DD;
    int t = threadIdx.x;
    float v0 = xr[t], v1 = xr[t+256], v2 = xr[t+512];
    red[t] = v0*v0 + v1*v1 + v2*v2;
    __syncthreads();
    for (int o = 128; o > 0; o >>= 1) { if (t < o) red[t] += red[t+o]; __syncthreads(); }
    float r = rsqrtf(red[0] * (1.0f/768.0f) + 1e-6f);
    size_t b = (size_t)row * DD;
    st_hilo(hi, lo, b+t,     w[t]*v0*r);
    st_hilo(hi, lo, b+t+256, w[t+256]*v1*r);
    st_hilo(hi, lo, b+t+512, w[t+512]*v2*r);
}

// ====== all weight transposes + hi/lo splits in ONE launch (2560 tile-blocks) ======
__global__ __launch_bounds__(256)
void wsplit_all(const float* __restrict__ wqkv, const float* __restrict__ wog,
                const float* __restrict__ wreso, const float* __restrict__ wc,
                const float* __restrict__ wp) {
    __shared__ float t[32][33];
    int bid = blockIdx.x;
    int tx = threadIdx.x & 31, ty = threadIdx.x >> 5;
    if (bid < 1600) {
        int n0 = (bid % 100) * 32, k0 = (bid / 100) * 32;
        int n = n0 + tx;
        for (int i = ty; i < 32; i += 8) {
            float v;
            int k = k0 + i;
            if (n < 2304)      v = wqkv[(size_t)k * 2304 + n];
            else if (n < 3072) v = wog[(size_t)k * 768 + (n - 2304)];
            else if (n < 3120) v = wreso[(size_t)k * 48 + (n - 3072)];
            else               v = 0.f;
            t[i][tx] = v;
        }
        __syncthreads();
        for (int j = ty; j < 32; j += 8)
            st_hilo(g_wb_h, g_wb_l, (size_t)(n0 + j) * LATD + k0 + tx, t[tx][j]);
    } else if (bid < 1984) {
        int idx = bid - 1600;
        int n0 = (idx % 16) * 32, k0 = (idx / 16) * 32;
        for (int i = ty; i < 32; i += 8) t[i][tx] = wc[(size_t)(k0 + i) * 512 + n0 + tx];
        __syncthreads();
        for (int j = ty; j < 32; j += 8)
            st_hilo(g_wc_h, g_wc_l, (size_t)(n0 + j) * DD + k0 + tx, t[tx][j]);
    } else {
        int idx = bid - 1984;
        int n0 = (idx % 24) * 32, k0 = (idx / 24) * 32;
        for (int i = ty; i < 32; i += 8) t[i][tx] = wp[(size_t)(k0 + i) * DD + n0 + tx];
        __syncthreads();
        for (int j = ty; j < 32; j += 8)
            st_hilo(g_wp_h, g_wp_l, (size_t)(n0 + j) * DD + k0 + tx, t[tx][j]);
    }
}

// ================= gate / decay / df coefficients =================
__global__ __launch_bounds__(256) void coef_kernel(const float* __restrict__ hd,
                                                   const float* __restrict__ temp) {
    int idx = blockIdx.x*blockDim.x + threadIdx.x;
    if (idx >= BHL) return;
    int h = idx % HH;
    int m = idx / HH;
    int l = m % LL, b = m / LL;
    float d = 0.3f + 0.65f / (1.f + expf(-hd[h]));
    d = fminf(fmaxf(d, 1e-5f), 0.999f);
    float one_m = 1.f - d;
    const float* p = g_reso + (size_t)m*128 + h*4;
    float sa = 1.f / (1.f + expf(-p[0]));
    float sp = PI_F / (1.f + expf(-p[1]));
    float ca = 1.f / (1.f + expf(-p[2]));
    float cp = PI_F / (1.f + expf(-p[3]));
    float inner = sa * ca * cosf(sp - cp) * temp[0];
    float gate = 1.2f / (1.f + expf(-inner)) - 0.1f;
    gate = fminf(fmaxf(gate, 0.05f), 0.95f);
    float df = expf((float)(l+1) * logf(d));
    float inv = 1.f / (df + 1e-8f);
    size_t o = ((size_t)(b*HH + h))*LL + l;
    g_cA[o] = gate * one_m * inv;
    g_cB[o] = one_m * inv;
    g_df[o] = df;
}

// ===== per-head RMS + RoPE + elu+1 prep -> bf16 hi/lo [B,H,L,64]; V' [B,H,L,72] =====
__global__ __launch_bounds__(384) void prep_kernel(const float* __restrict__ wqn,
                                                   const float* __restrict__ wkn) {
    int m = blockIdx.x;
    int l = m % LL, b = m / LL;
    int h = threadIdx.x >> 5;
    int lane = threadIdx.x & 31;
    int bh = b*HH + h;
    const float* base = g_qkv + (size_t)m*(3*DD) + h*64;
    float invd = expf(-(float)lane * 0.28782313662425575f);
    float ang = (float)l * invd;
    float c = cosf(ang), s = sinf(ang);
    size_t ob = ((size_t)bh*LL + l)*64;
    {
        float a = base[lane], bv = base[lane+32];
        float ss = a*a + bv*bv;
        #pragma unroll
        for (int o = 16; o > 0; o >>= 1) ss += __shfl_xor_sync(0xffffffffu, ss, o);
        float r = rsqrtf(ss * (1.0f/64.0f) + 1e-6f);
        a *= r * wqn[lane]; bv *= r * wqn[lane+32];
        float ra = a*c - bv*s, rb = bv*c + a*s;
        st_hilo(g_qh, g_ql, ob+lane,    ra > 0.f ? ra + 1.f : expf(ra));
        st_hilo(g_qh, g_ql, ob+lane+32, rb > 0.f ? rb + 1.f : expf(rb));
    }
    {
        const float* kp = base + DD;
        float a = kp[lane], bv = kp[lane+32];
        float ss = a*a + bv*bv;
        #pragma unroll
        for (int o = 16; o > 0; o >>= 1) ss += __shfl_xor_sync(0xffffffffu, ss, o);
        float r = rsqrtf(ss * (1.0f/64.0f) + 1e-6f);
        a *= r * wkn[lane]; bv *= r * wkn[lane+32];
        float ra = a*c - bv*s, rb = bv*c + a*s;
        st_hilo(g_kh, g_kl, ob+lane,    ra > 0.f ? ra + 1.f : expf(ra));
        st_hilo(g_kh, g_kl, ob+lane+32, rb > 0.f ? rb + 1.f : expf(rb));
    }
    {
        const float* vp = base + 2*DD;
        float cA = g_cA[(size_t)bh*LL + l];
        size_t vb = ((size_t)bh*LL + l)*72;
        st_hilo(g_vh, g_vl, vb+lane,    vp[lane]   * cA);
        st_hilo(g_vh, g_vl, vb+lane+32, vp[lane+32]* cA);
        if (lane < 8) {
            float val = (lane == 0) ? g_cB[(size_t)bh*LL + l] : 0.f;
            st_hilo(g_vh, g_vl, vb+64+lane, val);
        }
    }
}

// ================= HMMA causal linear attention (round-8 proven config) =================
#define AQM 9216                    // one 64x72 bf16 matrix
#define ABUF (4*AQM)                // Kh,Kl,Vh,Vl per buffer
#define ATTN_SMEM (2*AQM + 2*ABUF + 256)   // 92416

__global__ __launch_bounds__(128)
void attn_mma() {
    extern __shared__ __align__(128) char asmem[];
    uint32_t sb = smem_u32(asmem);
    int qb = 15 - blockIdx.x;
    int h = blockIdx.y, b = blockIdx.z;
    int bh = b*HH + h;
    int tid = threadIdx.x, w = tid >> 5, lane = tid & 31;
    float* dfs = (float*)(asmem + 2*AQM + 2*ABUF);

    {
        size_t qoff = ((size_t)bh*LL + qb*64)*64;
        const __nv_bfloat16* Qh_g = g_qh + qoff;
        const __nv_bfloat16* Ql_g = g_ql + qoff;
        #pragma unroll
        for (int it = 0; it < 8; it++) {
            int i = it * 128 + tid;
            int m = i >> 9, r = (i >> 3) & 63, q = i & 7;
            const __nv_bfloat16* src = (m ? Ql_g : Qh_g) + r * 64 + q * 8;
            cp16(sb + m * AQM + (r * 72 + q * 8) * 2, src);
        }
    }
    if (tid < 64) dfs[tid] = g_df[(size_t)bh*LL + qb*64 + tid];

    auto issue = [&](int kt, int buf) {
        size_t koff = ((size_t)bh*LL + kt*64);
        const __nv_bfloat16* Ks_g[2] = { g_kh + koff*64, g_kl + koff*64 };
        const __nv_bfloat16* Vs_g[2] = { g_vh + koff*72, g_vl + koff*72 };
        uint32_t dbase = sb + 2*AQM + buf*ABUF;
        #pragma unroll
        for (int it = 0; it < 8; it++) {
            int i = it * 128 + tid;
            int m = i >> 9, r = (i >> 3) & 63, q = i & 7;
            cp16(dbase + m*AQM + (r*72 + q*8)*2, Ks_g[m] + (size_t)r*64 + q*8);
        }
        #pragma unroll
        for (int it = 0; it < 9; it++) {
            int i = it * 128 + tid;
            int m = i / 576, rem = i % 576, r = rem / 9, q = rem % 9;
            cp16(dbase + 2*AQM + m*AQM + (r*72 + q*8)*2, Vs_g[m] + (size_t)r*72 + q*8);
        }
    };

    issue(0, 0); cp_commit();

    float acc[9][4];
    #pragma unroll
    for (int i = 0; i < 9; i++)
        #pragma unroll
        for (int j = 0; j < 4; j++) acc[i][j] = 0.f;

    int nk = qb + 1;
    for (int kt = 0; kt < nk; kt++) {
        if (kt + 1 < nk) { issue(kt + 1, (kt + 1) & 1); cp_commit(); cp_wait<1>(); }
        else cp_wait<0>();
        __syncthreads();
        uint32_t kb = sb + 2*AQM + (kt & 1)*ABUF;

        float sacc[8][4];
        #pragma unroll
        for (int i = 0; i < 8; i++)
            #pragma unroll
            for (int j = 0; j < 4; j++) sacc[i][j] = 0.f;

        uint32_t qh4[4][4], ql4[4][4];
        #pragma unroll
        for (int ks = 0; ks < 4; ks++) {
            uint32_t ad = sb + ((w*16 + (lane & 15))*72 + ks*16 + (lane >> 4)*8)*2;
            ldsm4(qh4[ks], ad);
            ldsm4(ql4[ks], ad + AQM);
        }
        #pragma unroll
        for (int nt = 0; nt < 8; nt++) {
            #pragma unroll
            for (int ks = 0; ks < 4; ks++) {
                uint32_t kh2[2], kl2[2];
                uint32_t kd = kb + ((nt*8 + (lane & 7))*72 + ks*16 + ((lane >> 3) & 1)*8)*2;
                ldsm2(kh2, kd);
                ldsm2(kl2, kd + AQM);
                mma16816(sacc[nt], qh4[ks], kh2);
                mma16816(sacc[nt], qh4[ks], kl2);
                mma16816(sacc[nt], ql4[ks], kh2);
            }
        }

        if (kt == qb) {
            int rb0 = w*16 + (lane >> 2);
            #pragma unroll
            for (int nt = 0; nt < 8; nt++) {
                int cc = nt*8 + (lane & 3)*2;
                if (cc     > rb0)     sacc[nt][0] = 0.f;
                if (cc + 1 > rb0)     sacc[nt][1] = 0.f;
                if (cc     > rb0 + 8) sacc[nt][2] = 0.f;
                if (cc + 1 > rb0 + 8) sacc[nt][3] = 0.f;
            }
        }

        uint32_t Sh[4][4], Sl[4][4];
        #pragma unroll
        for (int j = 0; j < 4; j++) {
            hilo2(sacc[2*j][0],   sacc[2*j][1],   Sh[j][0], Sl[j][0]);
            hilo2(sacc[2*j][2],   sacc[2*j][3],   Sh[j][1], Sl[j][1]);
            hilo2(sacc[2*j+1][0], sacc[2*j+1][1], Sh[j][2], Sl[j][2]);
            hilo2(sacc[2*j+1][2], sacc[2*j+1][3], Sh[j][3], Sl[j][3]);
        }

        #pragma unroll
        for (int j = 0; j < 4; j++) {
            #pragma unroll
            for (int nt2 = 0; nt2 < 9; nt2++) {
                uint32_t vh2[2], vl2[2];
                uint32_t vd = kb + 2*AQM + ((j*16 + (lane & 15))*72 + nt2*8)*2;
                ldsm2t(vh2, vd);
                ldsm2t(vl2, vd + AQM);
                mma16816(acc[nt2], Sh[j], vh2);
                mma16816(acc[nt2], Sl[j], vh2);
                mma16816(acc[nt2], Sh[j], vl2);
            }
        }
        __syncthreads();
    }

    float dn0 = __shfl_sync(0xffffffffu, acc[8][0], lane & 28);
    float dn1 = __shfl_sync(0xffffffffu, acc[8][2], lane & 28);
    int rloc = w*16 + (lane >> 2);
    float df0 = dfs[rloc], df1 = dfs[rloc + 8];
    float sc0 = df0 / fmaxf(df0 * dn0, 1e-5f);
    float sc1 = df1 / fmaxf(df1 * dn1, 1e-5f);
    int mrow = b*LL + qb*64 + rloc;
    #pragma unroll
    for (int nt2 = 0; nt2 < 8; nt2++) {
        int e = nt2*8 + (lane & 3)*2;
        *(float2*)(g_o + (size_t)mrow*DD + h*64 + e) =
            make_float2(acc[nt2][0]*sc0, acc[nt2][1]*sc0);
        *(float2*)(g_o + (size_t)(mrow+8)*DD + h*64 + e) =
            make_float2(acc[nt2][2]*sc1, acc[nt2][3]*sc1);
    }
}

// ================= host =================
#define SMEM64  (2*(2*64*80  + 2*MATB_B))   // 61440
#define SMEM128 (2*(2*128*80 + 2*MATB_B))   // 81920

extern "C" void kernel_launch(void* const* d_in, const int* in_sizes, int n_in,
                              void* d_out, int out_size) {
    const float* x           = (const float*)d_in[0];
    const float* w_ln        = (const float*)d_in[1];
    const float* w_compress  = (const float*)d_in[2];
    const float* w_qkv       = (const float*)d_in[3];
    const float* w_reso      = (const float*)d_in[4];
    const float* w_qn        = (const float*)d_in[5];
    const float* w_kn        = (const float*)d_in[6];
    const float* head_decay  = (const float*)d_in[7];
    const float* temperature = (const float*)d_in[8];
    const float* w_out_gate  = (const float*)d_in[9];
    const float* w_proj      = (const float*)d_in[10];
    const float* w_memnorm   = (const float*)d_in[11];

    float *p_latent, *p_qkv, *p_og, *p_o;
    cudaGetSymbolAddress((void**)&p_latent, g_latent);
    cudaGetSymbolAddress((void**)&p_qkv, g_qkv);
    cudaGetSymbolAddress((void**)&p_og, g_og);
    cudaGetSymbolAddress((void**)&p_o, g_o);
    __nv_bfloat16 *xnh,*xnl,*lath,*latl,*onh,*onl,*wch,*wcl,*wbh,*wbl,*wph,*wpl;
    cudaGetSymbolAddress((void**)&xnh, g_xn_h);  cudaGetSymbolAddress((void**)&xnl, g_xn_l);
    cudaGetSymbolAddress((void**)&lath, g_lat_h); cudaGetSymbolAddress((void**)&latl, g_lat_l);
    cudaGetSymbolAddress((void**)&onh, g_on_h);  cudaGetSymbolAddress((void**)&onl, g_on_l);
    cudaGetSymbolAddress((void**)&wch, g_wc_h);  cudaGetSymbolAddress((void**)&wcl, g_wc_l);
    cudaGetSymbolAddress((void**)&wbh, g_wb_h);  cudaGetSymbolAddress((void**)&wbl, g_wb_l);
    cudaGetSymbolAddress((void**)&wph, g_wp_h);  cudaGetSymbolAddress((void**)&wpl, g_wp_l);

    cudaFuncSetAttribute(mma_gemm<64>,  cudaFuncAttributeMaxDynamicSharedMemorySize, SMEM64);
    cudaFuncSetAttribute(mma_gemm<128>, cudaFuncAttributeMaxDynamicSharedMemorySize, SMEM128);
    cudaFuncSetAttribute(attn_mma, cudaFuncAttributeMaxDynamicSharedMemorySize, ATTN_SMEM);

    // 0. all weight splits in one launch
    wsplit_all<<<2560, 256>>>(w_qkv, w_out_gate, w_reso, w_compress, w_proj);
    // 1. xn = RMS(x) -> bf16 hi/lo
    rms_hilo<<<MM, 256>>>(x, w_ln, xnh, xnl);
    // 2. latent = silu(xn @ Wc)  [BM=64: 128 blocks]
    mma_gemm<64><<<dim3(LATD/128, MM/64), 128, SMEM64>>>(xnh, xnl, wch, wcl,
        p_latent, LATD, DD, 3, nullptr, lath, latl);
    // 3. merged qkv | og | reso = latent @ Wbig (2048x3200x512)  [400 blocks]
    mma_gemm<128><<<dim3(NBIG/128, MM/128), 128, SMEM128>>>(lath, latl, wbh, wbl,
        p_qkv, NBIG, LATD, 4, nullptr, nullptr, nullptr);
    // 4. coefficients, q/k prep
    coef_kernel<<<(BHL + 255)/256, 256>>>(head_decay, temperature);
    prep_kernel<<<MM, 384>>>(w_qn, w_kn);
    // 5. attention [384 blocks x 128 threads, round-8 config]
    attn_mma<<<dim3(16, HH, BB), 128, ATTN_SMEM>>>();
    // 6. on = RMS(o); out = (on @ Wproj) * og   [BM=64: 192 blocks]
    rms_hilo<<<MM, 256>>>(p_o, w_memnorm, onh, onl);
    mma_gemm<64><<<dim3(DD/128, MM/64), 128, SMEM64>>>(onh, onl, wph, wpl,
        (float*)d_out, DD, DD, 2, p_og, nullptr, nullptr);
}

// round 14
// speedup vs baseline: 1.1599x; 1.1599x over previous
#include <cuda_runtime.h>
#include <cuda_bf16.h>
#include <math.h>
#include <stdint.h>

#define BB 2
#define LL 1024
#define DD 768
#define HH 12
#define LATD 512
#define MM (BB*LL)   // 2048
#define BHL (BB*HH*LL)
#define NBIG 3200    // merged: 2304 qkv | 768 og | 48 reso | 80 pad
#define PI_F 3.14159265358979323846f

// ================= scratch (static device arrays; no allocation) =================
__device__ __align__(256) float g_latent[MM*LATD];
__device__ __align__(256) float g_qkv[MM*3*DD];
__device__ __align__(256) float g_reso[MM*128];        // padded stride 128
__device__ __align__(256) float g_og[MM*DD];
__device__ __align__(256) float g_cA[BHL];
__device__ __align__(256) float g_cB[BHL];
__device__ __align__(256) float g_df[BHL];
__device__ __align__(256) float g_o[MM*DD];
// bf16 hi/lo attention operands
__device__ __align__(256) __nv_bfloat16 g_qh[BHL*64], g_ql[BHL*64];
__device__ __align__(256) __nv_bfloat16 g_kh[BHL*64], g_kl[BHL*64];
__device__ __align__(256) __nv_bfloat16 g_vh[BHL*72], g_vl[BHL*72];  // V' (cA*v | cB | pad)
// bf16 hi/lo GEMM operands
__device__ __align__(256) __nv_bfloat16 g_xn_h[MM*DD],   g_xn_l[MM*DD];
__device__ __align__(256) __nv_bfloat16 g_lat_h[MM*LATD], g_lat_l[MM*LATD];
__device__ __align__(256) __nv_bfloat16 g_on_h[MM*DD],   g_on_l[MM*DD];
__device__ __align__(256) __nv_bfloat16 g_wc_h[LATD*DD],  g_wc_l[LATD*DD];     // [512][768]
__device__ __align__(256) __nv_bfloat16 g_wb_h[NBIG*LATD],g_wb_l[NBIG*LATD];   // [3200][512]
__device__ __align__(256) __nv_bfloat16 g_wp_h[DD*DD],    g_wp_l[DD*DD];       // [768][768]

// ================= PTX helpers (baseline sm_80+ features only) =================
__device__ __forceinline__ uint32_t smem_u32(const void* p) {
    uint32_t a;
    asm("{ .reg .u64 t; cvta.to.shared.u64 t, %1; cvt.u32.u64 %0, t; }" : "=r"(a) : "l"(p));
    return a;
}
__device__ __forceinline__ void cp16(uint32_t dst, const void* src) {
    asm volatile("cp.async.cg.shared.global [%0], [%1], 16;" :: "r"(dst), "l"(src));
}
__device__ __forceinline__ void cp_commit() { asm volatile("cp.async.commit_group;" ::: "memory"); }
template<int N> __device__ __forceinline__ void cp_wait() {
    asm volatile("cp.async.wait_group %0;" :: "n"(N) : "memory");
}
__device__ __forceinline__ void ldsm4(uint32_t* r, uint32_t addr) {
    asm volatile("ldmatrix.sync.aligned.m8n8.x4.shared.b16 {%0,%1,%2,%3}, [%4];"
        : "=r"(r[0]), "=r"(r[1]), "=r"(r[2]), "=r"(r[3]) : "r"(addr));
}
__device__ __forceinline__ void ldsm2(uint32_t* r, uint32_t addr) {
    asm volatile("ldmatrix.sync.aligned.m8n8.x2.shared.b16 {%0,%1}, [%2];"
        : "=r"(r[0]), "=r"(r[1]) : "r"(addr));
}
__device__ __forceinline__ void ldsm2t(uint32_t* r, uint32_t addr) {
    asm volatile("ldmatrix.sync.aligned.m8n8.x2.trans.shared.b16 {%0,%1}, [%2];"
        : "=r"(r[0]), "=r"(r[1]) : "r"(addr));
}
__device__ __forceinline__ void mma16816(float* d, const uint32_t* a, const uint32_t* b) {
    asm volatile(
        "mma.sync.aligned.m16n8k16.row.col.f32.bf16.bf16.f32 "
        "{%0,%1,%2,%3}, {%4,%5,%6,%7}, {%8,%9}, {%0,%1,%2,%3};"
        : "+f"(d[0]), "+f"(d[1]), "+f"(d[2]), "+f"(d[3])
        : "r"(a[0]), "r"(a[1]), "r"(a[2]), "r"(a[3]), "r"(b[0]), "r"(b[1]));
}
__device__ __forceinline__ void hilo2(float a, float b, uint32_t& hi, uint32_t& lo) {
    __nv_bfloat16 ha = __float2bfloat16(a), hb = __float2bfloat16(b);
    __nv_bfloat16 la = __float2bfloat16(a - __bfloat162float(ha));
    __nv_bfloat16 lb = __float2bfloat16(b - __bfloat162float(hb));
    hi = (uint32_t)__bfloat16_as_ushort(ha) | ((uint32_t)__bfloat16_as_ushort(hb) << 16);
    lo = (uint32_t)__bfloat16_as_ushort(la) | ((uint32_t)__bfloat16_as_ushort(lb) << 16);
}
__device__ __forceinline__ void st_hilo(__nv_bfloat16* hi, __nv_bfloat16* lo, size_t idx, float v) {
    __nv_bfloat16 h = __float2bfloat16(v);
    hi[idx] = h;
    lo[idx] = __float2bfloat16(v - __bfloat162float(h));
}

// ================= HMMA GEMM: C[M,N] = A[M,K] @ B[N,K]^T =================
// act: 0=none, 1=silu, 2=mul aux, 3=silu+emit hi/lo ONLY (fp32 dead), 4=merged epilogue
// R11-proven config: 8 warps (2m x 4n), warp tile (BM/2)x32, 2 blocks/SM.
#define MATB_B 10240               // 128 rows * 40 bf16 * 2B

template<int BM>
__global__ __launch_bounds__(256, 2)
void mma_gemm(const __nv_bfloat16* __restrict__ Ahi, const __nv_bfloat16* __restrict__ Alo,
              const __nv_bfloat16* __restrict__ Bhi, const __nv_bfloat16* __restrict__ Blo,
              float* __restrict__ C, int N, int K, int act,
              const float* __restrict__ aux,
              __nv_bfloat16* __restrict__ Chi, __nv_bfloat16* __restrict__ Clo)
{
    constexpr int MATB_A = BM * 80;
    constexpr int BUFB = 2*MATB_A + 2*MATB_B;
    constexpr int MT = BM / 32;
    extern __shared__ __align__(128) char smem[];
    uint32_t sb = smem_u32(smem);
    int tid = threadIdx.x;
    int wid = tid >> 5, lane = tid & 31;
    int row0 = blockIdx.y * BM;
    int n0   = blockIdx.x * 128;
    int wm0 = (wid & 1) * (BM/2);
    int wn0 = (wid >> 1) * 32;

    const __nv_bfloat16* amats[2] = { Ahi + (size_t)row0 * K, Alo + (size_t)row0 * K };
    const __nv_bfloat16* bmats[2] = { Bhi + (size_t)n0   * K, Blo + (size_t)n0   * K };

    float acc[MT][4][4];
    #pragma unroll
    for (int mt = 0; mt < MT; mt++)
        #pragma unroll
        for (int nt = 0; nt < 4; nt++)
            #pragma unroll
            for (int i = 0; i < 4; i++) acc[mt][nt][i] = 0.f;

    auto fill = [&](int c, int buf) {
        int k0 = c * 32;
        uint32_t dbase = sb + buf * BUFB;
        #pragma unroll
        for (int m = 0; m < 2; m++) {
            const __nv_bfloat16* srcm = amats[m] + k0;
            #pragma unroll
            for (int g = 0; g < BM/64; g++) {
                int idx = g * 256 + tid;
                int row = idx >> 2, q = idx & 3;
                cp16(dbase + m * MATB_A + row * 80 + q * 16,
                     srcm + (size_t)row * K + q * 8);
            }
        }
        #pragma unroll
        for (int m = 0; m < 2; m++) {
            const __nv_bfloat16* srcm = bmats[m] + k0;
            #pragma unroll
            for (int g = 0; g < 2; g++) {
                int idx = g * 256 + tid;
                int row = idx >> 2, q = idx & 3;
                cp16(dbase + 2*MATB_A + m * MATB_B + row * 80 + q * 16,
                     srcm + (size_t)row * K + q * 8);
            }
        }
    };

    int NC = K >> 5;
    fill(0, 0); cp_commit();

    for (int c = 0; c < NC; c++) {
        if (c + 1 < NC) { fill(c + 1, (c + 1) & 1); cp_commit(); cp_wait<1>(); }
        else cp_wait<0>();
        __syncthreads();

        uint32_t base = sb + (c & 1) * BUFB;
        #pragma unroll
        for (int ks = 0; ks < 2; ks++) {
            uint32_t ah[MT][4], al[MT][4], bh[4][2], bl[4][2];
            int arow = wm0 + (lane & 15);
            int acol = ks * 16 + (lane >> 4) * 8;
            #pragma unroll
            for (int mt = 0; mt < MT; mt++) {
                uint32_t ad = base + (arow + mt * 16) * 80 + acol * 2;
                ldsm4(ah[mt], ad);
                ldsm4(al[mt], ad + MATB_A);
            }
            int brow = wn0 + (lane & 7);
            int bcol = ks * 16 + ((lane >> 3) & 1) * 8;
            #pragma unroll
            for (int nt = 0; nt < 4; nt++) {
                uint32_t bd = base + 2*MATB_A + (brow + nt * 8) * 80 + bcol * 2;
                ldsm2(bh[nt], bd);
                ldsm2(bl[nt], bd + MATB_B);
            }
            #pragma unroll
            for (int mt = 0; mt < MT; mt++)
                #pragma unroll
                for (int nt = 0; nt < 4; nt++) {
                    mma16816(acc[mt][nt], ah[mt], bh[nt]);
                    mma16816(acc[mt][nt], ah[mt], bl[nt]);
                    mma16816(acc[mt][nt], al[mt], bh[nt]);
                }
        }
        __syncthreads();
    }

    // ---- epilogue (merged-segment dispatch for act==4)
    float* Cp = C; int Nout = N; int coff = n0; int a = act;
    if (act == 4) {
        if (n0 < 2304)       { Cp = g_qkv;  Nout = 2304; coff = n0;        a = 0; }
        else if (n0 < 3072)  { Cp = g_og;   Nout = 768;  coff = n0 - 2304; a = 1; }
        else                 { Cp = g_reso; Nout = 128;  coff = 0;         a = 0; }
    }
    #pragma unroll
    for (int mt = 0; mt < MT; mt++) {
        #pragma unroll
        for (int nt = 0; nt < 4; nt++) {
            int r1 = row0 + wm0 + mt * 16 + (lane >> 2);
            int ct = wn0 + nt * 8 + (lane & 3) * 2;
            #pragma unroll
            for (int hf = 0; hf < 2; hf++) {
                int rr = r1 + hf * 8;
                float v0 = acc[mt][nt][hf * 2], v1 = acc[mt][nt][hf * 2 + 1];
                size_t gidx = (size_t)rr * Nout + coff + ct;
                if (a == 1 || a == 3) {
                    v0 = v0 / (1.f + expf(-v0));
                    v1 = v1 / (1.f + expf(-v1));
                } else if (a == 2) {
                    float2 ax = *(const float2*)(aux + gidx);
                    v0 *= ax.x; v1 *= ax.y;
                }
                if (a != 3)                        // act3: fp32 output is dead, skip
                    *(float2*)(Cp + gidx) = make_float2(v0, v1);
                if (a == 3) {
                    __nv_bfloat16 h0 = __float2bfloat16(v0);
                    __nv_bfloat16 h1 = __float2bfloat16(v1);
                    __nv_bfloat162 hh; hh.x = h0; hh.y = h1;
                    *(__nv_bfloat162*)(Chi + gidx) = hh;
                    __nv_bfloat162 ll;
                    ll.x = __float2bfloat16(v0 - __bfloat162float(h0));
                    ll.y = __float2bfloat16(v1 - __bfloat162float(h1));
                    *(__nv_bfloat162*)(Clo + gidx) = ll;
                }
            }
        }
    }
}

// ================= RMSNorm over 768 -> bf16 hi/lo =================
__global__ __launch_bounds__(256) void rms_hilo(const float* __restrict__ x,
                                                const float* __restrict__ w,
                                                __nv_bfloat16* __restrict__ hi,
                                                __nv_bfloat16* __restrict__ lo) {
    __shared__ float red[256];
    int row = blockIdx.x;
    const float* xr = x + (size_t)row * DD;
    int t = threadIdx.x;
    float v0 = xr[t], v1 = xr[t+256], v2 = xr[t+512];
    red[t] = v0*v0 + v1*v1 + v2*v2;
    __syncthreads();
    for (int o = 128; o > 0; o >>= 1) { if (t < o) red[t] += red[t+o]; __syncthreads(); }
    float r = rsqrtf(red[0] * (1.0f/768.0f) + 1e-6f);
    size_t b = (size_t)row * DD;
    st_hilo(hi, lo, b+t,     w[t]*v0*r);
    st_hilo(hi, lo, b+t+256, w[t+256]*v1*r);
    st_hilo(hi, lo, b+t+512, w[t+512]*v2*r);
}

// ====== all weight transposes + hi/lo splits in ONE launch (2560 tile-blocks) ======
__global__ __launch_bounds__(256)
void wsplit_all(const float* __restrict__ wqkv, const float* __restrict__ wog,
                const float* __restrict__ wreso, const float* __restrict__ wc,
                const float* __restrict__ wp) {
    __shared__ float t[32][33];
    int bid = blockIdx.x;
    int tx = threadIdx.x & 31, ty = threadIdx.x >> 5;
    if (bid < 1600) {
        int n0 = (bid % 100) * 32, k0 = (bid / 100) * 32;
        int n = n0 + tx;
        for (int i = ty; i < 32; i += 8) {
            float v;
            int k = k0 + i;
            if (n < 2304)      v = wqkv[(size_t)k * 2304 + n];
            else if (n < 3072) v = wog[(size_t)k * 768 + (n - 2304)];
            else if (n < 3120) v = wreso[(size_t)k * 48 + (n - 3072)];
            else               v = 0.f;
            t[i][tx] = v;
        }
        __syncthreads();
        for (int j = ty; j < 32; j += 8)
            st_hilo(g_wb_h, g_wb_l, (size_t)(n0 + j) * LATD + k0 + tx, t[tx][j]);
    } else if (bid < 1984) {
        int idx = bid - 1600;
        int n0 = (idx % 16) * 32, k0 = (idx / 16) * 32;
        for (int i = ty; i < 32; i += 8) t[i][tx] = wc[(size_t)(k0 + i) * 512 + n0 + tx];
        __syncthreads();
        for (int j = ty; j < 32; j += 8)
            st_hilo(g_wc_h, g_wc_l, (size_t)(n0 + j) * DD + k0 + tx, t[tx][j]);
    } else {
        int idx = bid - 1984;
        int n0 = (idx % 24) * 32, k0 = (idx / 24) * 32;
        for (int i = ty; i < 32; i += 8) t[i][tx] = wp[(size_t)(k0 + i) * DD + n0 + tx];
        __syncthreads();
        for (int j = ty; j < 32; j += 8)
            st_hilo(g_wp_h, g_wp_l, (size_t)(n0 + j) * DD + k0 + tx, t[tx][j]);
    }
}

// ================= gate / decay / df coefficients =================
__global__ __launch_bounds__(256) void coef_kernel(const float* __restrict__ hd,
                                                   const float* __restrict__ temp) {
    int idx = blockIdx.x*blockDim.x + threadIdx.x;
    if (idx >= BHL) return;
    int h = idx % HH;
    int m = idx / HH;
    int l = m % LL, b = m / LL;
    float d = 0.3f + 0.65f / (1.f + expf(-hd[h]));
    d = fminf(fmaxf(d, 1e-5f), 0.999f);
    float one_m = 1.f - d;
    const float* p = g_reso + (size_t)m*128 + h*4;
    float sa = 1.f / (1.f + expf(-p[0]));
    float sp = PI_F / (1.f + expf(-p[1]));
    float ca = 1.f / (1.f + expf(-p[2]));
    float cp = PI_F / (1.f + expf(-p[3]));
    float inner = sa * ca * cosf(sp - cp) * temp[0];
    float gate = 1.2f / (1.f + expf(-inner)) - 0.1f;
    gate = fminf(fmaxf(gate, 0.05f), 0.95f);
    float df = expf((float)(l+1) * logf(d));
    float inv = 1.f / (df + 1e-8f);
    size_t o = ((size_t)(b*HH + h))*LL + l;
    g_cA[o] = gate * one_m * inv;
    g_cB[o] = one_m * inv;
    g_df[o] = df;
}

// ===== per-head RMS + RoPE + elu+1 prep -> bf16 hi/lo [B,H,L,64]; V' [B,H,L,72] =====
__global__ __launch_bounds__(384) void prep_kernel(const float* __restrict__ wqn,
                                                   const float* __restrict__ wkn) {
    int m = blockIdx.x;
    int l = m % LL, b = m / LL;
    int h = threadIdx.x >> 5;
    int lane = threadIdx.x & 31;
    int bh = b*HH + h;
    const float* base = g_qkv + (size_t)m*(3*DD) + h*64;
    float invd = expf(-(float)lane * 0.28782313662425575f);
    float ang = (float)l * invd;
    float c = cosf(ang), s = sinf(ang);
    size_t ob = ((size_t)bh*LL + l)*64;
    {
        float a = base[lane], bv = base[lane+32];
        float ss = a*a + bv*bv;
        #pragma unroll
        for (int o = 16; o > 0; o >>= 1) ss += __shfl_xor_sync(0xffffffffu, ss, o);
        float r = rsqrtf(ss * (1.0f/64.0f) + 1e-6f);
        a *= r * wqn[lane]; bv *= r * wqn[lane+32];
        float ra = a*c - bv*s, rb = bv*c + a*s;
        st_hilo(g_qh, g_ql, ob+lane,    ra > 0.f ? ra + 1.f : expf(ra));
        st_hilo(g_qh, g_ql, ob+lane+32, rb > 0.f ? rb + 1.f : expf(rb));
    }
    {
        const float* kp = base + DD;
        float a = kp[lane], bv = kp[lane+32];
        float ss = a*a + bv*bv;
        #pragma unroll
        for (int o = 16; o > 0; o >>= 1) ss += __shfl_xor_sync(0xffffffffu, ss, o);
        float r = rsqrtf(ss * (1.0f/64.0f) + 1e-6f);
        a *= r * wkn[lane]; bv *= r * wkn[lane+32];
        float ra = a*c - bv*s, rb = bv*c + a*s;
        st_hilo(g_kh, g_kl, ob+lane,    ra > 0.f ? ra + 1.f : expf(ra));
        st_hilo(g_kh, g_kl, ob+lane+32, rb > 0.f ? rb + 1.f : expf(rb));
    }
    {
        const float* vp = base + 2*DD;
        float cA = g_cA[(size_t)bh*LL + l];
        size_t vb = ((size_t)bh*LL + l)*72;
        st_hilo(g_vh, g_vl, vb+lane,    vp[lane]   * cA);
        st_hilo(g_vh, g_vl, vb+lane+32, vp[lane+32]* cA);
        if (lane < 8) {
            float val = (lane == 0) ? g_cB[(size_t)bh*LL + l] : 0.f;
            st_hilo(g_vh, g_vl, vb+64+lane, val);
        }
    }
}

// ================= HMMA causal linear attention (R8 config + Q-fragment hoist) =================
#define AQM 9216                    // one 64x72 bf16 matrix
#define ABUF (4*AQM)                // Kh,Kl,Vh,Vl per buffer
#define ATTN_SMEM (2*AQM + 2*ABUF + 256)   // 92416

__global__ __launch_bounds__(128)
void attn_mma() {
    extern __shared__ __align__(128) char asmem[];
    uint32_t sb = smem_u32(asmem);
    int qb = 15 - blockIdx.x;
    int h = blockIdx.y, b = blockIdx.z;
    int bh = b*HH + h;
    int tid = threadIdx.x, w = tid >> 5, lane = tid & 31;
    float* dfs = (float*)(asmem + 2*AQM + 2*ABUF);

    // Q -> smem in its OWN commit group (waited once, fragments hoisted)
    {
        size_t qoff = ((size_t)bh*LL + qb*64)*64;
        const __nv_bfloat16* Qh_g = g_qh + qoff;
        const __nv_bfloat16* Ql_g = g_ql + qoff;
        #pragma unroll
        for (int it = 0; it < 8; it++) {
            int i = it * 128 + tid;
            int m = i >> 9, r = (i >> 3) & 63, q = i & 7;
            const __nv_bfloat16* src = (m ? Ql_g : Qh_g) + r * 64 + q * 8;
            cp16(sb + m * AQM + (r * 72 + q * 8) * 2, src);
        }
    }
    cp_commit();                                   // group: Q
    if (tid < 64) dfs[tid] = g_df[(size_t)bh*LL + qb*64 + tid];

    auto issue = [&](int kt, int buf) {
        size_t koff = ((size_t)bh*LL + kt*64);
        const __nv_bfloat16* Ks_g[2] = { g_kh + koff*64, g_kl + koff*64 };
        const __nv_bfloat16* Vs_g[2] = { g_vh + koff*72, g_vl + koff*72 };
        uint32_t dbase = sb + 2*AQM + buf*ABUF;
        #pragma unroll
        for (int it = 0; it < 8; it++) {
            int i = it * 128 + tid;
            int m = i >> 9, r = (i >> 3) & 63, q = i & 7;
            cp16(dbase + m*AQM + (r*72 + q*8)*2, Ks_g[m] + (size_t)r*64 + q*8);
        }
        #pragma unroll
        for (int it = 0; it < 9; it++) {
            int i = it * 128 + tid;
            int m = i / 576, rem = i % 576, r = rem / 9, q = rem % 9;
            cp16(dbase + 2*AQM + m*AQM + (r*72 + q*8)*2, Vs_g[m] + (size_t)r*72 + q*8);
        }
    };

    issue(0, 0); cp_commit();                      // group: tile 0
    cp_wait<1>();                                  // Q complete (tile 0 may be in flight)
    __syncthreads();

    // hoisted Q fragments (invariant across all k-tiles)
    uint32_t qh4[4][4], ql4[4][4];
    #pragma unroll
    for (int ks = 0; ks < 4; ks++) {
        uint32_t ad = sb + ((w*16 + (lane & 15))*72 + ks*16 + (lane >> 4)*8)*2;
        ldsm4(qh4[ks], ad);
        ldsm4(ql4[ks], ad + AQM);
    }

    float acc[9][4];
    #pragma unroll
    for (int i = 0; i < 9; i++)
        #pragma unroll
        for (int j = 0; j < 4; j++) acc[i][j] = 0.f;

    int nk = qb + 1;
    for (int kt = 0; kt < nk; kt++) {
        if (kt + 1 < nk) { issue(kt + 1, (kt + 1) & 1); cp_commit(); cp_wait<1>(); }
        else cp_wait<0>();
        __syncthreads();
        uint32_t kb = sb + 2*AQM + (kt & 1)*ABUF;

        float sacc[8][4];
        #pragma unroll
        for (int i = 0; i < 8; i++)
            #pragma unroll
            for (int j = 0; j < 4; j++) sacc[i][j] = 0.f;

        #pragma unroll
        for (int nt = 0; nt < 8; nt++) {
            #pragma unroll
            for (int ks = 0; ks < 4; ks++) {
                uint32_t kh2[2], kl2[2];
                uint32_t kd = kb + ((nt*8 + (lane & 7))*72 + ks*16 + ((lane >> 3) & 1)*8)*2;
                ldsm2(kh2, kd);
                ldsm2(kl2, kd + AQM);
                mma16816(sacc[nt], qh4[ks], kh2);
                mma16816(sacc[nt], qh4[ks], kl2);
                mma16816(sacc[nt], ql4[ks], kh2);
            }
        }

        if (kt == qb) {
            int rb0 = w*16 + (lane >> 2);
            #pragma unroll
            for (int nt = 0; nt < 8; nt++) {
                int cc = nt*8 + (lane & 3)*2;
                if (cc     > rb0)     sacc[nt][0] = 0.f;
                if (cc + 1 > rb0)     sacc[nt][1] = 0.f;
                if (cc     > rb0 + 8) sacc[nt][2] = 0.f;
                if (cc + 1 > rb0 + 8) sacc[nt][3] = 0.f;
            }
        }

        uint32_t Sh[4][4], Sl[4][4];
        #pragma unroll
        for (int j = 0; j < 4; j++) {
            hilo2(sacc[2*j][0],   sacc[2*j][1],   Sh[j][0], Sl[j][0]);
            hilo2(sacc[2*j][2],   sacc[2*j][3],   Sh[j][1], Sl[j][1]);
            hilo2(sacc[2*j+1][0], sacc[2*j+1][1], Sh[j][2], Sl[j][2]);
            hilo2(sacc[2*j+1][2], sacc[2*j+1][3], Sh[j][3], Sl[j][3]);
        }

        #pragma unroll
        for (int j = 0; j < 4; j++) {
            #pragma unroll
            for (int nt2 = 0; nt2 < 9; nt2++) {
                uint32_t vh2[2], vl2[2];
                uint32_t vd = kb + 2*AQM + ((j*16 + (lane & 15))*72 + nt2*8)*2;
                ldsm2t(vh2, vd);
                ldsm2t(vl2, vd + AQM);
                mma16816(acc[nt2], Sh[j], vh2);
                mma16816(acc[nt2], Sl[j], vh2);
                mma16816(acc[nt2], Sh[j], vl2);
            }
        }
        __syncthreads();
    }

    float dn0 = __shfl_sync(0xffffffffu, acc[8][0], lane & 28);
    float dn1 = __shfl_sync(0xffffffffu, acc[8][2], lane & 28);
    int rloc = w*16 + (lane >> 2);
    float df0 = dfs[rloc], df1 = dfs[rloc + 8];
    float sc0 = df0 / fmaxf(df0 * dn0, 1e-5f);
    float sc1 = df1 / fmaxf(df1 * dn1, 1e-5f);
    int mrow = b*LL + qb*64 + rloc;
    #pragma unroll
    for (int nt2 = 0; nt2 < 8; nt2++) {
        int e = nt2*8 + (lane & 3)*2;
        *(float2*)(g_o + (size_t)mrow*DD + h*64 + e) =
            make_float2(acc[nt2][0]*sc0, acc[nt2][1]*sc0);
        *(float2*)(g_o + (size_t)(mrow+8)*DD + h*64 + e) =
            make_float2(acc[nt2][2]*sc1, acc[nt2][3]*sc1);
    }
}

// ================= host =================
#define SMEM64  (2*(2*64*80  + 2*MATB_B))   // 61440
#define SMEM128 (2*(2*128*80 + 2*MATB_B))   // 81920

extern "C" void kernel_launch(void* const* d_in, const int* in_sizes, int n_in,
                              void* d_out, int out_size) {
    const float* x           = (const float*)d_in[0];
    const float* w_ln        = (const float*)d_in[1];
    const float* w_compress  = (const float*)d_in[2];
    const float* w_qkv       = (const float*)d_in[3];
    const float* w_reso      = (const float*)d_in[4];
    const float* w_qn        = (const float*)d_in[5];
    const float* w_kn        = (const float*)d_in[6];
    const float* head_decay  = (const float*)d_in[7];
    const float* temperature = (const float*)d_in[8];
    const float* w_out_gate  = (const float*)d_in[9];
    const float* w_proj      = (const float*)d_in[10];
    const float* w_memnorm   = (const float*)d_in[11];

    float *p_latent, *p_qkv, *p_og, *p_o;
    cudaGetSymbolAddress((void**)&p_latent, g_latent);
    cudaGetSymbolAddress((void**)&p_qkv, g_qkv);
    cudaGetSymbolAddress((void**)&p_og, g_og);
    cudaGetSymbolAddress((void**)&p_o, g_o);
    __nv_bfloat16 *xnh,*xnl,*lath,*latl,*onh,*onl,*wch,*wcl,*wbh,*wbl,*wph,*wpl;
    cudaGetSymbolAddress((void**)&xnh, g_xn_h);  cudaGetSymbolAddress((void**)&xnl, g_xn_l);
    cudaGetSymbolAddress((void**)&lath, g_lat_h); cudaGetSymbolAddress((void**)&latl, g_lat_l);
    cudaGetSymbolAddress((void**)&onh, g_on_h);  cudaGetSymbolAddress((void**)&onl, g_on_l);
    cudaGetSymbolAddress((void**)&wch, g_wc_h);  cudaGetSymbolAddress((void**)&wcl, g_wc_l);
    cudaGetSymbolAddress((void**)&wbh, g_wb_h);  cudaGetSymbolAddress((void**)&wbl, g_wb_l);
    cudaGetSymbolAddress((void**)&wph, g_wp_h);  cudaGetSymbolAddress((void**)&wpl, g_wp_l);

    cudaFuncSetAttribute(mma_gemm<64>,  cudaFuncAttributeMaxDynamicSharedMemorySize, SMEM64);
    cudaFuncSetAttribute(mma_gemm<128>, cudaFuncAttributeMaxDynamicSharedMemorySize, SMEM128);
    cudaFuncSetAttribute(attn_mma, cudaFuncAttributeMaxDynamicSharedMemorySize, ATTN_SMEM);

    // 0. all weight splits in one launch
    wsplit_all<<<2560, 256>>>(w_qkv, w_out_gate, w_reso, w_compress, w_proj);
    // 1. xn = RMS(x) -> bf16 hi/lo
    rms_hilo<<<MM, 256>>>(x, w_ln, xnh, xnl);
    // 2. latent = silu(xn @ Wc) -> hi/lo only  [BM=64: 128 blocks, 2/SM]
    mma_gemm<64><<<dim3(LATD/128, MM/64), 256, SMEM64>>>(xnh, xnl, wch, wcl,
        p_latent, LATD, DD, 3, nullptr, lath, latl);
    // 3. merged qkv | og | reso = latent @ Wbig (2048x3200x512)  [400 blocks, 2/SM]
    mma_gemm<128><<<dim3(NBIG/128, MM/128), 256, SMEM128>>>(lath, latl, wbh, wbl,
        p_qkv, NBIG, LATD, 4, nullptr, nullptr, nullptr);
    // 4. coefficients, q/k prep
    coef_kernel<<<(BHL + 255)/256, 256>>>(head_decay, temperature);
    prep_kernel<<<MM, 384>>>(w_qn, w_kn);
    // 5. attention [384 blocks x 128 threads, Q-hoisted]
    attn_mma<<<dim3(16, HH, BB), 128, ATTN_SMEM>>>();
    // 6. on = RMS(o); out = (on @ Wproj) * og   [BM=64: 192 blocks]
    rms_hilo<<<MM, 256>>>(p_o, w_memnorm, onh, onl);
    mma_gemm<64><<<dim3(DD/128, MM/64), 256, SMEM64>>>(onh, onl, wph, wpl,
        (float*)d_out, DD, DD, 2, p_og, nullptr, nullptr);
}